// round 14
// baseline (speedup 1.0000x reference)
#include <cuda_runtime.h>
#include <math.h>

#define NT 512
typedef unsigned long long ull;

// ---- packed f32x2 helpers (sm_103a) ----
__device__ __forceinline__ ull pk2(float lo, float hi) {
    ull r; asm("mov.b64 %0, {%1,%2};" : "=l"(r) : "f"(lo), "f"(hi)); return r;
}
__device__ __forceinline__ float2 upk2(ull v) {
    float2 r; asm("mov.b64 {%0,%1}, %2;" : "=f"(r.x), "=f"(r.y) : "l"(v)); return r;
}
__device__ __forceinline__ ull ffma2(ull a, ull b, ull c) {
    ull d; asm("fma.rn.f32x2 %0, %1, %2, %3;" : "=l"(d) : "l"(a), "l"(b), "l"(c)); return d;
}
__device__ __forceinline__ void loadx(const float* p, ull* xp) {
    const float4* p4 = (const float4*)p;
#pragma unroll
    for (int i = 0; i < 4; i++) {
        float4 v = p4[i];
        xp[2*i]   = pk2(v.x, v.y);
        xp[2*i+1] = pk2(v.z, v.w);
    }
}
__device__ __forceinline__ float dot16p(const ull* xp, const float4* w4) {
    ull a0 = 0ull, a1 = 0ull;
#pragma unroll
    for (int i = 0; i < 4; i++) {
        float4 w = w4[i];
        a0 = ffma2(xp[2*i],   pk2(w.x, w.y), a0);
        a1 = ffma2(xp[2*i+1], pk2(w.z, w.w), a1);
    }
    float2 s0 = upk2(a0), s1 = upk2(a1);
    return (s0.x + s1.x) + (s0.y + s1.y);
}

__global__ __launch_bounds__(NT, 1) void fused_kernel(
    const float* __restrict__ t,
    const float* __restrict__ gat_W, const float* __restrict__ a_src, const float* __restrict__ a_dst,
    const float* __restrict__ te_W, const float* __restrict__ te_b, const float* __restrict__ pe,
    const float* __restrict__ qkv_W, const float* __restrict__ qkv_b,
    const float* __restrict__ out_W, const float* __restrict__ out_b,
    const float* __restrict__ ln1_g, const float* __restrict__ ln1_b,
    const float* __restrict__ ff1_W, const float* __restrict__ ff1_b,
    const float* __restrict__ ff2_W, const float* __restrict__ ff2_b,
    const float* __restrict__ ln2_g, const float* __restrict__ ln2_b,
    const float* __restrict__ an_W, const float* __restrict__ an_b,
    const float* __restrict__ pr_W, const float* __restrict__ pr_b,
    float* __restrict__ out)
{
    const int tid  = threadIdx.x;
    const int warp = tid >> 5;
    const int lane = tid & 31;

    // ---- decoder weight prefetch (registers; hidden behind encoder) ----
    const int row = blockIdx.x * 16 + warp;   // 0..159
    const float4* wp = (row < 32) ? (const float4*)(an_W + row * 768)
                                  : (const float4*)(pr_W + (row - 32) * 768);
    float bias_reg = (row < 32) ? an_b[row] : pr_b[row - 32];
    float4 wreg[6];
#pragma unroll
    for (int i = 0; i < 6; i++) wreg[i] = __ldg(wp + i * 32 + lane);

    extern __shared__ float sm[];
    float* s_qkvW = sm;            // 96 rows * 20 = 1920
    float* s_qkvb = sm + 1920;     // 96
    float* s_outW = sm + 2016;     // 512
    float* s_outb = sm + 2528;     // 32
    float* s_ln1g = sm + 2560;     // 32
    float* s_ln1b = sm + 2592;     // 32
    float* s_ff1W = sm + 2624;     // 128 rows * 20 = 2560
    float* s_ff1b = sm + 5184;     // 128
    float* s_ff2W = sm + 5312;     // 32 rows * 68 = 2176
    float* s_ff2b = sm + 7488;     // 32
    float* s_ln2g = sm + 7520;     // 32
    float* s_ln2b = sm + 7552;     // 32
    float* s_teW  = sm + 7584;     // 256
    float* s_teb  = sm + 7840;     // 16
    float* s_pe   = sm + 7856;     // 48
    float* A_h    = sm + 7904;     // 48*20 (window-major: w*16+n)
    float* A_xe   = sm + 8864;     // 48*20 (BATCH-major: b*3+w)
    float* A_qkv  = sm + 9824;     // 48*52 (batch-major)
    float* A_hid  = sm + 12320;    // 48*68 (batch-major)
    float* A_e    = sm + 15584;    // 96

    if (warp < 3) {
        // ======== prologue compute: warps 0-2 ========
        if (tid < 48) {
            float x0 = __ldg(t + tid*3), x1 = __ldg(t + tid*3 + 1), x2 = __ldg(t + tid*3 + 2);
            float hrow[16];
            float es = 0.f, ed = 0.f;
#pragma unroll
            for (int f = 0; f < 16; f++) {
                float hv = x0*__ldg(gat_W+f) + x1*__ldg(gat_W+16+f) + x2*__ldg(gat_W+32+f);
                hrow[f] = hv;
                es += hv * __ldg(a_src+f);
                ed += hv * __ldg(a_dst+f);
            }
#pragma unroll
            for (int i = 0; i < 4; i++)
                *(float4*)(A_h + tid*20 + i*4) = make_float4(hrow[4*i], hrow[4*i+1], hrow[4*i+2], hrow[4*i+3]);
            A_e[tid] = es;
            A_e[48 + tid] = ed;
        }
        asm volatile("bar.sync 1, 96;" ::: "memory");

        // P2: softmax + aggregate(8 dims) + ELU + swap + te (2 threads/token)
        {
            const int tok = tid >> 1, hf = tid & 1;   // tok = w*16+n
            const int w = tok >> 4, n = tok & 15;
            float ed = A_e[48 + tok];
            float vals[16], mx = -1e30f;
#pragma unroll
            for (int s = 0; s < 16; s++) {
                float e = A_e[w * 16 + s] + ed;
                e = (e > 0.f) ? e : 0.2f * e;
                vals[s] = e; mx = fmaxf(mx, e);
            }
            float sum = 0.f;
#pragma unroll
            for (int s = 0; s < 16; s++) { vals[s] = __expf(vals[s] - mx); sum += vals[s]; }
            float inv = 1.f / sum;
            ull acc[4] = {0,0,0,0};
#pragma unroll
            for (int ss = 0; ss < 16; ss++) {
                const float4* hr = (const float4*)(A_h + (w * 16 + ss) * 20 + hf * 8);
                float4 h0 = hr[0], h1 = hr[1];
                ull av = pk2(vals[ss] * inv, vals[ss] * inv);
                acc[0] = ffma2(av, pk2(h0.x, h0.y), acc[0]);
                acc[1] = ffma2(av, pk2(h0.z, h0.w), acc[1]);
                acc[2] = ffma2(av, pk2(h1.x, h1.y), acc[2]);
                acc[3] = ffma2(av, pk2(h1.z, h1.w), acc[3]);
            }
            float x8[8];
#pragma unroll
            for (int i = 0; i < 4; i++) {
                float2 v = upk2(acc[i]);
                x8[2*i]   = (v.x > 0.f) ? v.x : (__expf(v.x) - 1.f);
                x8[2*i+1] = (v.y > 0.f) ? v.y : (__expf(v.y) - 1.f);
            }
            asm volatile("bar.sync 2, 160;" ::: "memory");   // wait te staging
            float full[16];
#pragma unroll
            for (int e = 0; e < 8; e++) {
                float o = __shfl_xor_sync(0xffffffffu, x8[e], 1);
                if (hf == 0) { full[e] = x8[e]; full[8+e] = o; }
                else         { full[e] = o;     full[8+e] = x8[e]; }
            }
            ull xp[8];
#pragma unroll
            for (int i = 0; i < 8; i++) xp[i] = pk2(full[2*i], full[2*i+1]);
            float y[8];
#pragma unroll
            for (int k = 0; k < 8; k++) {
                int d = hf * 8 + k;
                y[k] = s_teb[d] + s_pe[w * 16 + d] +
                       dot16p(xp, (const float4*)(s_teW + d * 16));
            }
            // batch-major store: row = n*3 + w
            *(float4*)(A_xe + (n*3 + w) * 20 + hf * 8)     = make_float4(y[0], y[1], y[2], y[3]);
            *(float4*)(A_xe + (n*3 + w) * 20 + hf * 8 + 4) = make_float4(y[4], y[5], y[6], y[7]);
        }
    } else if (warp < 5) {
        // ======== te staging + biases: warps 3-4 ========
        if (warp == 3) {
            const float4* s = (const float4*)te_W;  float4* d = (float4*)s_teW;
#pragma unroll
            for (int i = lane; i < 64; i += 32) d[i] = __ldg(s + i);
        } else {
            if (lane < 16) s_teb[lane] = __ldg(te_b + lane);
            for (int i = lane; i < 48; i += 32) s_pe[i] = __ldg(pe + i);
        }
        asm volatile("bar.arrive 2, 160;" ::: "memory");
        const int tid3 = tid - 96;   // 0..63
        for (int i = tid3; i < 96; i += 64) s_qkvb[i] = __ldg(qkv_b + i);
        for (int i = tid3; i < 128; i += 64) s_ff1b[i] = __ldg(ff1_b + i);
        if (tid3 < 32) {
            s_outb[tid3] = __ldg(out_b + tid3);
            s_ln1g[tid3] = __ldg(ln1_g + tid3);
            s_ln1b[tid3] = __ldg(ln1_b + tid3);
            s_ff2b[tid3] = __ldg(ff2_b + tid3);
            s_ln2g[tid3] = __ldg(ln2_g + tid3);
            s_ln2b[tid3] = __ldg(ln2_b + tid3);
        }
    } else {
        // ======== bulk weight staging: warps 5-15 (352 threads), all float4 ========
        const int tid5 = tid - 160;
        const float4* s1 = (const float4*)qkv_W;     // 384 f4; stride 20
        for (int i = tid5; i < 384; i += 352)
            *(float4*)(s_qkvW + (i >> 2) * 20 + (i & 3) * 4) = __ldg(s1 + i);
        const float4* s2 = (const float4*)out_W;  float4* d2 = (float4*)s_outW;
        for (int i = tid5; i < 128; i += 352) d2[i] = __ldg(s2 + i);
        const float4* s3 = (const float4*)ff1_W;     // 512 f4; stride 20
        for (int i = tid5; i < 512; i += 352)
            *(float4*)(s_ff1W + (i >> 2) * 20 + (i & 3) * 4) = __ldg(s3 + i);
        const float4* s4 = (const float4*)ff2_W;     // 512 f4; stride 68
        for (int i = tid5; i < 512; i += 352)
            *(float4*)(s_ff2W + (i >> 4) * 68 + (i & 15) * 4) = __ldg(s4 + i);
    }
    __syncthreads();

    const float inv_sqrt_hd = 0.35355339059327373f;

    // ================= layer loop: warp = batch, NO block barriers =================
    // token row (batch-major) = warp*3 + w
    for (int l = 0; l < 2; l++) {
        // ---- qkv: lanes 0-23 (tok3 = lane>>3, r8 = lane&7), 6 outputs/lane ----
        if (lane < 24) {
            const int trow = warp * 3 + (lane >> 3);
            const int r8l = lane & 7;
            ull xp[8]; loadx(A_xe + trow * 20, xp);
#pragma unroll
            for (int k = 0; k < 6; k++) {
                int j = r8l + 8 * k;
                A_qkv[trow * 52 + j] = s_qkvb[l * 48 + j] +
                    dot16p(xp, (const float4*)(s_qkvW + (l * 48 + j) * 20));
            }
        }
        __syncwarp();

        // ---- attention + out-proj + residual + LN1: lanes 0-11 (4/token) ----
        if (lane < 12) {
            const int atok = lane >> 2;       // window of query
            const int q4   = lane & 3;
            const int h2   = q4 >> 1;
            const int hf   = q4 & 1;
            const int trow = warp * 3 + atok;
            float4 qv = *(const float4*)(A_qkv + trow * 52 + h2 * 8 + hf * 4);
            float sc[3], mx = -1e30f;
#pragma unroll
            for (int ks = 0; ks < 3; ks++) {
                float4 kv = *(const float4*)(A_qkv + (warp * 3 + ks) * 52 + 16 + h2 * 8 + hf * 4);
                float p = qv.x*kv.x + qv.y*kv.y + qv.z*kv.z + qv.w*kv.w;
                p += __shfl_xor_sync(0xfffu, p, 1);
                p *= inv_sqrt_hd;
                sc[ks] = p; mx = fmaxf(mx, p);
            }
            float sum = 0.f;
#pragma unroll
            for (int ks = 0; ks < 3; ks++) { sc[ks] = __expf(sc[ks] - mx); sum += sc[ks]; }
            float inv = 1.f / sum;
            float c0 = 0.f, c1 = 0.f, c2 = 0.f, c3 = 0.f;
#pragma unroll
            for (int ks = 0; ks < 3; ks++) {
                float4 vv = *(const float4*)(A_qkv + (warp * 3 + ks) * 52 + 32 + h2 * 8 + hf * 4);
                float w = sc[ks];
                c0 += w * vv.x; c1 += w * vv.y; c2 += w * vv.z; c3 += w * vv.w;
            }
            c0 *= inv; c1 *= inv; c2 *= inv; c3 *= inv;
            float part[16];
#pragma unroll
            for (int d = 0; d < 16; d++) {
                float4 w = *(const float4*)(s_outW + l * 256 + d * 16 + q4 * 4);
                part[d] = c0*w.x + c1*w.y + c2*w.z + c3*w.w;
            }
            const int bm = (q4 < 2) ? 0 : 8;
            const int bo = 8 - bm;
            float s1v[8];
#pragma unroll
            for (int i = 0; i < 8; i++)
                s1v[i] = part[bm + i] + __shfl_xor_sync(0xfffu, part[bo + i], 2);
            const int mr = (q4 & 1) * 4;
            const int orr = 4 - mr;
            float y[4];
#pragma unroll
            for (int k = 0; k < 4; k++)
                y[k] = s1v[mr + k] + __shfl_xor_sync(0xfffu, s1v[orr + k], 1);
            float4 resid = *(const float4*)(A_xe + trow * 20 + q4 * 4);
            y[0] += resid.x + s_outb[l*16 + q4*4 + 0];
            y[1] += resid.y + s_outb[l*16 + q4*4 + 1];
            y[2] += resid.z + s_outb[l*16 + q4*4 + 2];
            y[3] += resid.w + s_outb[l*16 + q4*4 + 3];
            float ls = y[0]+y[1]+y[2]+y[3];
            float lq = y[0]*y[0]+y[1]*y[1]+y[2]*y[2]+y[3]*y[3];
            ls += __shfl_xor_sync(0xfffu, ls, 1);
            lq += __shfl_xor_sync(0xfffu, lq, 1);
            ls += __shfl_xor_sync(0xfffu, ls, 2);
            lq += __shfl_xor_sync(0xfffu, lq, 2);
            float m = ls * 0.0625f;
            float rin = rsqrtf(lq * 0.0625f - m * m + 1e-5f);
#pragma unroll
            for (int k = 0; k < 4; k++) {
                int d = q4 * 4 + k;
                y[k] = (y[k] - m) * rin * s_ln1g[l * 16 + d] + s_ln1b[l * 16 + d];
            }
            *(float4*)(A_xe + trow * 20 + q4 * 4) = make_float4(y[0], y[1], y[2], y[3]);
        }
        __syncwarp();

        // ---- ff1 (relu): lanes 0-23, 8 outputs/lane (f = r8 + 8k) ----
        if (lane < 24) {
            const int trow = warp * 3 + (lane >> 3);
            const int r8l = lane & 7;
            ull xp[8]; loadx(A_xe + trow * 20, xp);
#pragma unroll
            for (int k = 0; k < 8; k++) {
                int f = r8l + 8 * k;
                A_hid[trow * 68 + f] = fmaxf(s_ff1b[l * 64 + f] +
                    dot16p(xp, (const float4*)(s_ff1W + (l * 64 + f) * 20)), 0.f);
            }
        }
        __syncwarp();

        // ---- ff2 + residual + LN2: lanes 0-11 (4/token; d = q4+4k, bank-free) ----
        if (lane < 12) {
            const int atok = lane >> 2, q4 = lane & 3;
            const int trow = warp * 3 + atok;
            const float4* hr = (const float4*)(A_hid + trow * 68);
            const float4* wr0 = (const float4*)(s_ff2W + l * 1088 + (q4 + 0)  * 68);
            const float4* wr1 = (const float4*)(s_ff2W + l * 1088 + (q4 + 4)  * 68);
            const float4* wr2 = (const float4*)(s_ff2W + l * 1088 + (q4 + 8)  * 68);
            const float4* wr3 = (const float4*)(s_ff2W + l * 1088 + (q4 + 12) * 68);
            ull a0[4] = {0,0,0,0}, a1[4] = {0,0,0,0};
#pragma unroll
            for (int i = 0; i < 16; i++) {
                float4 h4 = hr[i];
                ull h0 = pk2(h4.x, h4.y), h1 = pk2(h4.z, h4.w);
                float4 w0 = wr0[i], w1 = wr1[i], w2 = wr2[i], w3 = wr3[i];
                a0[0] = ffma2(h0, pk2(w0.x, w0.y), a0[0]); a1[0] = ffma2(h1, pk2(w0.z, w0.w), a1[0]);
                a0[1] = ffma2(h0, pk2(w1.x, w1.y), a0[1]); a1[1] = ffma2(h1, pk2(w1.z, w1.w), a1[1]);
                a0[2] = ffma2(h0, pk2(w2.x, w2.y), a0[2]); a1[2] = ffma2(h1, pk2(w2.z, w2.w), a1[2]);
                a0[3] = ffma2(h0, pk2(w3.x, w3.y), a0[3]); a1[3] = ffma2(h1, pk2(w3.z, w3.w), a1[3]);
            }
            float y[4], ls = 0.f, lq = 0.f;
#pragma unroll
            for (int k = 0; k < 4; k++) {
                int d = q4 + 4 * k;
                float2 s0 = upk2(a0[k]), s1 = upk2(a1[k]);
                y[k] = (s0.x + s1.x) + (s0.y + s1.y) + s_ff2b[l * 16 + d] + A_xe[trow * 20 + d];
                ls += y[k]; lq += y[k] * y[k];
            }
            ls += __shfl_xor_sync(0xfffu, ls, 1);
            lq += __shfl_xor_sync(0xfffu, lq, 1);
            ls += __shfl_xor_sync(0xfffu, ls, 2);
            lq += __shfl_xor_sync(0xfffu, lq, 2);
            float m = ls * 0.0625f;
            float rin = rsqrtf(lq * 0.0625f - m * m + 1e-5f);
#pragma unroll
            for (int k = 0; k < 4; k++) {
                int d = q4 + 4 * k;
                A_xe[trow * 20 + d] = (y[k] - m) * rin * s_ln2g[l * 16 + d] + s_ln2b[l * 16 + d];
            }
        }
        __syncwarp();
    }
    __syncthreads();

    // ---- decoder: warp = output row; latent[j], j = n*48 + w*16 + d -> A_xe[(n*3+w)*20 + d]
    {
        ull a0 = 0ull, a1 = 0ull;
#pragma unroll
        for (int i = 0; i < 6; i++) {
            int j = i * 128 + 4 * lane;
            int n = j / 48, rem = j - n * 48;
            int ww = rem >> 4, d = rem & 15;
            float4 x = *(const float4*)(A_xe + (n * 3 + ww) * 20 + d);
            a0 = ffma2(pk2(x.x, x.y), pk2(wreg[i].x, wreg[i].y), a0);
            a1 = ffma2(pk2(x.z, x.w), pk2(wreg[i].z, wreg[i].w), a1);
        }
        float2 s0 = upk2(a0), s1 = upk2(a1);
        float s = (s0.x + s1.x) + (s0.y + s1.y);
#pragma unroll
        for (int o = 16; o; o >>= 1) s += __shfl_xor_sync(0xffffffffu, s, o);
        if (lane == 0) {
            s += bias_reg;
            if (row >= 32) s = 1.f / (1.f + __expf(-s));
            out[row] = s;
        }
    }
}

extern "C" void kernel_launch(void* const* d_in, const int* in_sizes, int n_in,
                              void* d_out, int out_size) {
    const int smem_bytes = 15680 * 4;
    cudaFuncSetAttribute(fused_kernel, cudaFuncAttributeMaxDynamicSharedMemorySize, smem_bytes);
    fused_kernel<<<10, NT, smem_bytes>>>(
        (const float*)d_in[0],
        (const float*)d_in[2], (const float*)d_in[3], (const float*)d_in[4],
        (const float*)d_in[5], (const float*)d_in[6], (const float*)d_in[7],
        (const float*)d_in[8], (const float*)d_in[9],
        (const float*)d_in[10], (const float*)d_in[11],
        (const float*)d_in[12], (const float*)d_in[13],
        (const float*)d_in[14], (const float*)d_in[15],
        (const float*)d_in[16], (const float*)d_in[17],
        (const float*)d_in[18], (const float*)d_in[19],
        (const float*)d_in[20], (const float*)d_in[21],
        (const float*)d_in[22], (const float*)d_in[23],
        (float*)d_out);
}

// round 15
// speedup vs baseline: 1.1561x; 1.1561x over previous
#include <cuda_runtime.h>
#include <math.h>

#define NT 512
typedef unsigned long long ull;

// ---- packed f32x2 helpers (sm_103a) ----
__device__ __forceinline__ ull pk2(float lo, float hi) {
    ull r; asm("mov.b64 %0, {%1,%2};" : "=l"(r) : "f"(lo), "f"(hi)); return r;
}
__device__ __forceinline__ float2 upk2(ull v) {
    float2 r; asm("mov.b64 {%0,%1}, %2;" : "=f"(r.x), "=f"(r.y) : "l"(v)); return r;
}
__device__ __forceinline__ ull ffma2(ull a, ull b, ull c) {
    ull d; asm("fma.rn.f32x2 %0, %1, %2, %3;" : "=l"(d) : "l"(a), "l"(b), "l"(c)); return d;
}
__device__ __forceinline__ void loadx(const float* p, ull* xp) {
    const float4* p4 = (const float4*)p;
#pragma unroll
    for (int i = 0; i < 4; i++) {
        float4 v = p4[i];
        xp[2*i]   = pk2(v.x, v.y);
        xp[2*i+1] = pk2(v.z, v.w);
    }
}
__device__ __forceinline__ float dot16p(const ull* xp, const float4* w4) {
    ull a0 = 0ull, a1 = 0ull;
#pragma unroll
    for (int i = 0; i < 4; i++) {
        float4 w = w4[i];
        a0 = ffma2(xp[2*i],   pk2(w.x, w.y), a0);
        a1 = ffma2(xp[2*i+1], pk2(w.z, w.w), a1);
    }
    float2 s0 = upk2(a0), s1 = upk2(a1);
    return (s0.x + s1.x) + (s0.y + s1.y);
}
__device__ __forceinline__ float dot16g(const ull* xp, const float4* __restrict__ w4) {
    float4 w0 = __ldg(w4), w1 = __ldg(w4+1), w2 = __ldg(w4+2), w3 = __ldg(w4+3);
    ull a0 = 0ull, a1 = 0ull;
    a0 = ffma2(xp[0], pk2(w0.x, w0.y), a0); a1 = ffma2(xp[1], pk2(w0.z, w0.w), a1);
    a0 = ffma2(xp[2], pk2(w1.x, w1.y), a0); a1 = ffma2(xp[3], pk2(w1.z, w1.w), a1);
    a0 = ffma2(xp[4], pk2(w2.x, w2.y), a0); a1 = ffma2(xp[5], pk2(w2.z, w2.w), a1);
    a0 = ffma2(xp[6], pk2(w3.x, w3.y), a0); a1 = ffma2(xp[7], pk2(w3.z, w3.w), a1);
    float2 s0 = upk2(a0), s1 = upk2(a1);
    return (s0.x + s1.x) + (s0.y + s1.y);
}

__global__ __launch_bounds__(NT, 1) void fused_kernel(
    const float* __restrict__ t,
    const float* __restrict__ gat_W, const float* __restrict__ a_src, const float* __restrict__ a_dst,
    const float* __restrict__ te_W, const float* __restrict__ te_b, const float* __restrict__ pe,
    const float* __restrict__ qkv_W, const float* __restrict__ qkv_b,
    const float* __restrict__ out_W, const float* __restrict__ out_b,
    const float* __restrict__ ln1_g, const float* __restrict__ ln1_b,
    const float* __restrict__ ff1_W, const float* __restrict__ ff1_b,
    const float* __restrict__ ff2_W, const float* __restrict__ ff2_b,
    const float* __restrict__ ln2_g, const float* __restrict__ ln2_b,
    const float* __restrict__ an_W, const float* __restrict__ an_b,
    const float* __restrict__ pr_W, const float* __restrict__ pr_b,
    float* __restrict__ out)
{
    const int tid  = threadIdx.x;
    const int warp = tid >> 5;
    const int lane = tid & 31;
    const int g    = warp & 1;
    const int tk   = g * 32 + lane;
    const int pp   = warp >> 1;
    const bool tok_ok = tk < 48;

    // ---- decoder weight prefetch (registers; hidden behind encoder) ----
    const int row = blockIdx.x * 16 + warp;   // 0..159
    const float4* wp = (row < 32) ? (const float4*)(an_W + row * 768)
                                  : (const float4*)(pr_W + (row - 32) * 768);
    float bias_reg = (row < 32) ? an_b[row] : pr_b[row - 32];
    float4 wreg[6];
#pragma unroll
    for (int i = 0; i < 6; i++) wreg[i] = __ldg(wp + i * 32 + lane);

    extern __shared__ float sm[];
    float* s_qkvW = sm;            // 1536
    float* s_qkvb = sm + 1536;     // 96
    float* s_outW = sm + 1632;     // 512
    float* s_outb = sm + 2144;     // 32
    float* s_ln1g = sm + 2176;     // 32
    float* s_ln1b = sm + 2208;     // 32
    float* s_ff1W = sm + 2240;     // 2048
    float* s_ff1b = sm + 4288;     // 128
    float* s_ff2W = sm + 4416;     // 2176 (stride 68)
    float* s_ff2b = sm + 6592;     // 32
    float* s_ln2g = sm + 6624;     // 32
    float* s_ln2b = sm + 6656;     // 32
    float* A_h    = sm + 6688;     // 48*20
    float* A_xe   = sm + 7648;     // 48*20
    float* A_qkv  = sm + 8608;     // 48*52
    float* A_hid  = sm + 11104;    // 48*68
    float* A_e    = sm + 14368;    // 96

    if (warp < 2) {
        // ======== overlapped prologue: GAT P1 + P2 (weights from L2) ========
        if (tid < 48) {
            float x0 = __ldg(t + tid*3), x1 = __ldg(t + tid*3 + 1), x2 = __ldg(t + tid*3 + 2);
            float hrow[16];
            float es = 0.f, ed = 0.f;
#pragma unroll
            for (int f = 0; f < 16; f++) {
                float hv = x0*__ldg(gat_W+f) + x1*__ldg(gat_W+16+f) + x2*__ldg(gat_W+32+f);
                hrow[f] = hv;
                es += hv * __ldg(a_src+f);
                ed += hv * __ldg(a_dst+f);
            }
#pragma unroll
            for (int i = 0; i < 4; i++)
                *(float4*)(A_h + tid*20 + i*4) = make_float4(hrow[4*i], hrow[4*i+1], hrow[4*i+2], hrow[4*i+3]);
            A_e[tid] = es;
            A_e[48 + tid] = ed;
        }
        __syncwarp();
        if (tid < 48) {
            int w = tid >> 4;
            float ed = A_e[48 + tid];
            float vals[16], mx = -1e30f;
#pragma unroll
            for (int s = 0; s < 16; s++) {
                float e = A_e[w * 16 + s] + ed;
                e = (e > 0.f) ? e : 0.2f * e;
                vals[s] = e; mx = fmaxf(mx, e);
            }
            float sum = 0.f;
#pragma unroll
            for (int s = 0; s < 16; s++) { vals[s] = __expf(vals[s] - mx); sum += vals[s]; }
            float inv = 1.f / sum;
            ull acc[8] = {0,0,0,0,0,0,0,0};
#pragma unroll
            for (int ss = 0; ss < 16; ss++) {
                const float4* hr = (const float4*)(A_h + (w * 16 + ss) * 20);
                ull av = pk2(vals[ss] * inv, vals[ss] * inv);
#pragma unroll
                for (int i = 0; i < 4; i++) {
                    float4 hv = hr[i];
                    acc[2*i]   = ffma2(av, pk2(hv.x, hv.y), acc[2*i]);
                    acc[2*i+1] = ffma2(av, pk2(hv.z, hv.w), acc[2*i+1]);
                }
            }
            ull xp[8];
#pragma unroll
            for (int i = 0; i < 8; i++) {
                float2 v = upk2(acc[i]);
                float a = (v.x > 0.f) ? v.x : (__expf(v.x) - 1.f);
                float b = (v.y > 0.f) ? v.y : (__expf(v.y) - 1.f);
                xp[i] = pk2(a, b);
            }
            float y[16];
#pragma unroll
            for (int d = 0; d < 16; d++)
                y[d] = __ldg(te_b + d) + __ldg(pe + w * 16 + d) +
                       dot16g(xp, (const float4*)(te_W + d * 16));
#pragma unroll
            for (int i = 0; i < 4; i++)
                *(float4*)(A_xe + tid*20 + i*4) = make_float4(y[4*i], y[4*i+1], y[4*i+2], y[4*i+3]);
        }
    } else {
        // ======== concurrent weight staging (warps 2-15) ========
        const int tid2 = tid - 64;
        const float4* s1 = (const float4*)qkv_W;  float4* d1 = (float4*)s_qkvW;
        for (int i = tid2; i < 384; i += 448) d1[i] = __ldg(s1 + i);
        const float4* s2 = (const float4*)out_W;  float4* d2 = (float4*)s_outW;
        for (int i = tid2; i < 128; i += 448) d2[i] = __ldg(s2 + i);
        const float4* s3 = (const float4*)ff1_W;  float4* d3 = (float4*)s_ff1W;
        for (int i = tid2; i < 512; i += 448) d3[i] = __ldg(s3 + i);
        const float4* s4 = (const float4*)ff2_W;     // remap to stride 68, float4
        for (int i = tid2; i < 512; i += 448)
            *(float4*)(s_ff2W + (i >> 4) * 68 + (i & 15) * 4) = __ldg(s4 + i);
        if (tid2 < 96)  s_qkvb[tid2] = __ldg(qkv_b + tid2);
        if (tid2 >= 96 && tid2 < 128)  s_outb[tid2-96]  = __ldg(out_b + tid2-96);
        if (tid2 >= 128 && tid2 < 160) s_ln1g[tid2-128] = __ldg(ln1_g + tid2-128);
        if (tid2 >= 160 && tid2 < 192) s_ln1b[tid2-160] = __ldg(ln1_b + tid2-160);
        if (tid2 >= 192 && tid2 < 320) s_ff1b[tid2-192] = __ldg(ff1_b + tid2-192);
        if (tid2 >= 320 && tid2 < 352) s_ff2b[tid2-320] = __ldg(ff2_b + tid2-320);
        if (tid2 >= 352 && tid2 < 384) s_ln2g[tid2-352] = __ldg(ln2_g + tid2-352);
        if (tid2 >= 384 && tid2 < 416) s_ln2b[tid2-384] = __ldg(ln2_b + tid2-384);
    }
    __syncthreads();

    const float inv_sqrt_hd = 0.35355339059327373f;

    for (int l = 0; l < 2; l++) {
        // ---- qkv (6 outputs per active lane; uniform weight rows) ----
        if (tok_ok) {
            ull xp[8]; loadx(A_xe + tk * 20, xp);
#pragma unroll
            for (int i6 = 0; i6 < 6; i6++) {
                int j = pp + i6 * 8;
                A_qkv[tk * 52 + j] = s_qkvb[l * 48 + j] +
                    dot16p(xp, (const float4*)(s_qkvW + l * 768 + j * 16));
            }
        }
        __syncthreads();

        // ---- attention + out-proj + residual + LN1 (192 threads = 4/token) ----
        if (tid < 192) {
            const int tk2 = tid >> 2;
            const int q4  = tid & 3;
            const int h2  = q4 >> 1;
            const int hf  = q4 & 1;
            const int b   = tk2 & 15;
            float4 qv = *(const float4*)(A_qkv + tk2 * 52 + h2 * 8 + hf * 4);
            float sc[3], mx = -1e30f;
#pragma unroll
            for (int ks = 0; ks < 3; ks++) {
                float4 kv = *(const float4*)(A_qkv + (ks * 16 + b) * 52 + 16 + h2 * 8 + hf * 4);
                float p = qv.x*kv.x + qv.y*kv.y + qv.z*kv.z + qv.w*kv.w;
                p += __shfl_xor_sync(0xffffffffu, p, 1);
                p *= inv_sqrt_hd;
                sc[ks] = p; mx = fmaxf(mx, p);
            }
            float sum = 0.f;
#pragma unroll
            for (int ks = 0; ks < 3; ks++) { sc[ks] = __expf(sc[ks] - mx); sum += sc[ks]; }
            float inv = 1.f / sum;
            float c0 = 0.f, c1 = 0.f, c2 = 0.f, c3 = 0.f;
#pragma unroll
            for (int ks = 0; ks < 3; ks++) {
                float4 vv = *(const float4*)(A_qkv + (ks * 16 + b) * 52 + 32 + h2 * 8 + hf * 4);
                float w = sc[ks];
                c0 += w * vv.x; c1 += w * vv.y; c2 += w * vv.z; c3 += w * vv.w;
            }
            c0 *= inv; c1 *= inv; c2 *= inv; c3 *= inv;
            float part[16];
#pragma unroll
            for (int d = 0; d < 16; d++) {
                float4 w = *(const float4*)(s_outW + l * 256 + d * 16 + q4 * 4);
                part[d] = c0*w.x + c1*w.y + c2*w.z + c3*w.w;
            }
            const int bm = (q4 < 2) ? 0 : 8;
            const int bo = 8 - bm;
            float s1v[8];
#pragma unroll
            for (int i = 0; i < 8; i++)
                s1v[i] = part[bm + i] + __shfl_xor_sync(0xffffffffu, part[bo + i], 2);
            const int mr = (q4 & 1) * 4;
            const int orr = 4 - mr;
            float y[4];
#pragma unroll
            for (int k = 0; k < 4; k++)
                y[k] = s1v[mr + k] + __shfl_xor_sync(0xffffffffu, s1v[orr + k], 1);
            float4 resid = *(const float4*)(A_xe + tk2 * 20 + q4 * 4);
            y[0] += resid.x + s_outb[l*16 + q4*4 + 0];
            y[1] += resid.y + s_outb[l*16 + q4*4 + 1];
            y[2] += resid.z + s_outb[l*16 + q4*4 + 2];
            y[3] += resid.w + s_outb[l*16 + q4*4 + 3];
            float ls = y[0]+y[1]+y[2]+y[3];
            float lq = y[0]*y[0]+y[1]*y[1]+y[2]*y[2]+y[3]*y[3];
            ls += __shfl_xor_sync(0xffffffffu, ls, 1);
            lq += __shfl_xor_sync(0xffffffffu, lq, 1);
            ls += __shfl_xor_sync(0xffffffffu, ls, 2);
            lq += __shfl_xor_sync(0xffffffffu, lq, 2);
            float m = ls * 0.0625f;
            float rin = rsqrtf(lq * 0.0625f - m * m + 1e-5f);
#pragma unroll
            for (int k = 0; k < 4; k++) {
                int d = q4 * 4 + k;
                y[k] = (y[k] - m) * rin * s_ln1g[l * 16 + d] + s_ln1b[l * 16 + d];
            }
            *(float4*)(A_xe + tk2 * 20 + q4 * 4) = make_float4(y[0], y[1], y[2], y[3]);
        }
        __syncthreads();

        // ---- ff1 (relu), 8 contiguous outputs per active lane ----
        if (tok_ok) {
            ull xp[8]; loadx(A_xe + tk * 20, xp);
            float y[8];
#pragma unroll
            for (int k = 0; k < 8; k++) {
                int f = pp * 8 + k;
                y[k] = fmaxf(s_ff1b[l * 64 + f] +
                             dot16p(xp, (const float4*)(s_ff1W + l * 1024 + f * 16)), 0.f);
            }
            *(float4*)(A_hid + tk * 68 + pp * 8)     = make_float4(y[0], y[1], y[2], y[3]);
            *(float4*)(A_hid + tk * 68 + pp * 8 + 4) = make_float4(y[4], y[5], y[6], y[7]);
        }
        __syncthreads();

        // ---- ff2 + residual + LN2 (384 threads = 8/token; K split across kh) ----
        if (tid < 384) {
            const int tk2 = tid >> 3;          // token
            const int q8  = tid & 7;
            const int og  = q8 & 3;            // output group: d = og + 4k
            const int kh  = q8 >> 2;           // K-half
            const float4* hr  = (const float4*)(A_hid + tk2 * 68 + kh * 32);
            const float4* wr0 = (const float4*)(s_ff2W + l * 1088 + (og + 0)  * 68 + kh * 32);
            const float4* wr1 = (const float4*)(s_ff2W + l * 1088 + (og + 4)  * 68 + kh * 32);
            const float4* wr2 = (const float4*)(s_ff2W + l * 1088 + (og + 8)  * 68 + kh * 32);
            const float4* wr3 = (const float4*)(s_ff2W + l * 1088 + (og + 12) * 68 + kh * 32);
            ull a0[4] = {0,0,0,0}, a1[4] = {0,0,0,0};
            const int rot = kh * 4;            // bank-stagger between K-halves
#pragma unroll
            for (int i = 0; i < 8; i++) {
                int c = (i + rot) & 7;
                float4 h4 = hr[c];
                ull h0 = pk2(h4.x, h4.y), h1 = pk2(h4.z, h4.w);
                float4 w0 = wr0[c], w1 = wr1[c], w2 = wr2[c], w3 = wr3[c];
                a0[0] = ffma2(h0, pk2(w0.x, w0.y), a0[0]); a1[0] = ffma2(h1, pk2(w0.z, w0.w), a1[0]);
                a0[1] = ffma2(h0, pk2(w1.x, w1.y), a0[1]); a1[1] = ffma2(h1, pk2(w1.z, w1.w), a1[1]);
                a0[2] = ffma2(h0, pk2(w2.x, w2.y), a0[2]); a1[2] = ffma2(h1, pk2(w2.z, w2.w), a1[2]);
                a0[3] = ffma2(h0, pk2(w3.x, w3.y), a0[3]); a1[3] = ffma2(h1, pk2(w3.z, w3.w), a1[3]);
            }
            // combine K-halves with partner (lane xor 4; tokens are 8-lane aligned)
            float y[4], ls = 0.f, lq = 0.f;
#pragma unroll
            for (int k = 0; k < 4; k++) {
                float2 s0 = upk2(a0[k]), s1 = upk2(a1[k]);
                float part = (s0.x + s1.x) + (s0.y + s1.y);
                part += __shfl_xor_sync(0xffffffffu, part, 4);
                int d = og + 4 * k;
                y[k] = part + s_ff2b[l * 16 + d] + A_xe[tk2 * 20 + d];
                ls += y[k]; lq += y[k] * y[k];
            }
            // LN reduce across og (both kh groups hold identical y -> reduce within kh)
            ls += __shfl_xor_sync(0xffffffffu, ls, 1);
            lq += __shfl_xor_sync(0xffffffffu, lq, 1);
            ls += __shfl_xor_sync(0xffffffffu, ls, 2);
            lq += __shfl_xor_sync(0xffffffffu, lq, 2);
            float m = ls * 0.0625f;
            float rin = rsqrtf(lq * 0.0625f - m * m + 1e-5f);
            if (kh == 0) {
#pragma unroll
                for (int k = 0; k < 4; k++) {
                    int d = og + 4 * k;
                    A_xe[tk2 * 20 + d] = (y[k] - m) * rin * s_ln2g[l * 16 + d] + s_ln2b[l * 16 + d];
                }
            }
        }
        __syncthreads();
    }

    // ---- decoder: warp = output row, latent from smem ----
    {
        ull a0 = 0ull, a1 = 0ull;
#pragma unroll
        for (int i = 0; i < 6; i++) {
            int j = i * 128 + 4 * lane;
            int n = j / 48, rem = j - n * 48;
            int ww = rem >> 4, d = rem & 15;
            float4 x = *(const float4*)(A_xe + (ww * 16 + n) * 20 + d);
            a0 = ffma2(pk2(x.x, x.y), pk2(wreg[i].x, wreg[i].y), a0);
            a1 = ffma2(pk2(x.z, x.w), pk2(wreg[i].z, wreg[i].w), a1);
        }
        float2 s0 = upk2(a0), s1 = upk2(a1);
        float s = (s0.x + s1.x) + (s0.y + s1.y);
#pragma unroll
        for (int o = 16; o; o >>= 1) s += __shfl_xor_sync(0xffffffffu, s, o);
        if (lane == 0) {
            s += bias_reg;
            if (row >= 32) s = 1.f / (1.f + __expf(-s));
            out[row] = s;
        }
    }
}

extern "C" void kernel_launch(void* const* d_in, const int* in_sizes, int n_in,
                              void* d_out, int out_size) {
    const int smem_bytes = 14464 * 4;
    cudaFuncSetAttribute(fused_kernel, cudaFuncAttributeMaxDynamicSharedMemorySize, smem_bytes);
    fused_kernel<<<10, NT, smem_bytes>>>(
        (const float*)d_in[0],
        (const float*)d_in[2], (const float*)d_in[3], (const float*)d_in[4],
        (const float*)d_in[5], (const float*)d_in[6], (const float*)d_in[7],
        (const float*)d_in[8], (const float*)d_in[9],
        (const float*)d_in[10], (const float*)d_in[11],
        (const float*)d_in[12], (const float*)d_in[13],
        (const float*)d_in[14], (const float*)d_in[15],
        (const float*)d_in[16], (const float*)d_in[17],
        (const float*)d_in[18], (const float*)d_in[19],
        (const float*)d_in[20], (const float*)d_in[21],
        (const float*)d_in[22], (const float*)d_in[23],
        (float*)d_out);
}

// round 16
// speedup vs baseline: 1.2931x; 1.1185x over previous
#include <cuda_runtime.h>
#include <math.h>

#define NT 512
typedef unsigned long long ull;

// ---- packed f32x2 helpers (sm_103a) ----
__device__ __forceinline__ ull pk2(float lo, float hi) {
    ull r; asm("mov.b64 %0, {%1,%2};" : "=l"(r) : "f"(lo), "f"(hi)); return r;
}
__device__ __forceinline__ float2 upk2(ull v) {
    float2 r; asm("mov.b64 {%0,%1}, %2;" : "=f"(r.x), "=f"(r.y) : "l"(v)); return r;
}
__device__ __forceinline__ ull ffma2(ull a, ull b, ull c) {
    ull d; asm("fma.rn.f32x2 %0, %1, %2, %3;" : "=l"(d) : "l"(a), "l"(b), "l"(c)); return d;
}
__device__ __forceinline__ void loadx(const float* p, ull* xp) {
    const float4* p4 = (const float4*)p;
#pragma unroll
    for (int i = 0; i < 4; i++) {
        float4 v = p4[i];
        xp[2*i]   = pk2(v.x, v.y);
        xp[2*i+1] = pk2(v.z, v.w);
    }
}
__device__ __forceinline__ float dot16p(const ull* xp, const float4* w4) {
    ull a0 = 0ull, a1 = 0ull;
#pragma unroll
    for (int i = 0; i < 4; i++) {
        float4 w = w4[i];
        a0 = ffma2(xp[2*i],   pk2(w.x, w.y), a0);
        a1 = ffma2(xp[2*i+1], pk2(w.z, w.w), a1);
    }
    float2 s0 = upk2(a0), s1 = upk2(a1);
    return (s0.x + s1.x) + (s0.y + s1.y);
}
__device__ __forceinline__ float dot16g(const ull* xp, const float4* __restrict__ w4) {
    float4 w0 = __ldg(w4), w1 = __ldg(w4+1), w2 = __ldg(w4+2), w3 = __ldg(w4+3);
    ull a0 = 0ull, a1 = 0ull;
    a0 = ffma2(xp[0], pk2(w0.x, w0.y), a0); a1 = ffma2(xp[1], pk2(w0.z, w0.w), a1);
    a0 = ffma2(xp[2], pk2(w1.x, w1.y), a0); a1 = ffma2(xp[3], pk2(w1.z, w1.w), a1);
    a0 = ffma2(xp[4], pk2(w2.x, w2.y), a0); a1 = ffma2(xp[5], pk2(w2.z, w2.w), a1);
    a0 = ffma2(xp[6], pk2(w3.x, w3.y), a0); a1 = ffma2(xp[7], pk2(w3.z, w3.w), a1);
    float2 s0 = upk2(a0), s1 = upk2(a1);
    return (s0.x + s1.x) + (s0.y + s1.y);
}

__global__ __launch_bounds__(NT, 1) void fused_kernel(
    const float* __restrict__ t,
    const float* __restrict__ gat_W, const float* __restrict__ a_src, const float* __restrict__ a_dst,
    const float* __restrict__ te_W, const float* __restrict__ te_b, const float* __restrict__ pe,
    const float* __restrict__ qkv_W, const float* __restrict__ qkv_b,
    const float* __restrict__ out_W, const float* __restrict__ out_b,
    const float* __restrict__ ln1_g, const float* __restrict__ ln1_b,
    const float* __restrict__ ff1_W, const float* __restrict__ ff1_b,
    const float* __restrict__ ff2_W, const float* __restrict__ ff2_b,
    const float* __restrict__ ln2_g, const float* __restrict__ ln2_b,
    const float* __restrict__ an_W, const float* __restrict__ an_b,
    const float* __restrict__ pr_W, const float* __restrict__ pr_b,
    float* __restrict__ out)
{
    const int tid  = threadIdx.x;
    const int warp = tid >> 5;
    const int lane = tid & 31;
    const int g    = warp & 1;
    const int tk   = g * 32 + lane;
    const int pp   = warp >> 1;
    const bool tok_ok = tk < 48;

    // ---- decoder weight prefetch (registers; hidden behind encoder) ----
    const int row = blockIdx.x * 16 + warp;   // 0..159
    const float4* wp = (row < 32) ? (const float4*)(an_W + row * 768)
                                  : (const float4*)(pr_W + (row - 32) * 768);
    float bias_reg = (row < 32) ? an_b[row] : pr_b[row - 32];
    float4 wreg[6];
#pragma unroll
    for (int i = 0; i < 6; i++) wreg[i] = __ldg(wp + i * 32 + lane);

    extern __shared__ float sm[];
    float* s_qkvW = sm;            // 1536
    float* s_qkvb = sm + 1536;     // 96
    float* s_outW = sm + 1632;     // 512
    float* s_outb = sm + 2144;     // 32
    float* s_ln1g = sm + 2176;     // 32
    float* s_ln1b = sm + 2208;     // 32
    float* s_ff1W = sm + 2240;     // 2048
    float* s_ff1b = sm + 4288;     // 128
    float* s_ff2W = sm + 4416;     // 2176 (stride 68)
    float* s_ff2b = sm + 6592;     // 32
    float* s_ln2g = sm + 6624;     // 32
    float* s_ln2b = sm + 6656;     // 32
    float* A_h    = sm + 6688;     // 48*20
    float* A_xe   = sm + 7648;     // 48*20
    float* A_qkv  = sm + 8608;     // 48*52
    float* A_hid  = sm + 11104;    // 48*68
    float* A_e    = sm + 14368;    // 96

    if (warp < 2) {
        // ======== overlapped prologue: GAT P1 + P2 (weights from L2) ========
        if (tid < 48) {
            float x0 = __ldg(t + tid*3), x1 = __ldg(t + tid*3 + 1), x2 = __ldg(t + tid*3 + 2);
            float hrow[16];
            float es = 0.f, ed = 0.f;
#pragma unroll
            for (int f = 0; f < 16; f++) {
                float hv = x0*__ldg(gat_W+f) + x1*__ldg(gat_W+16+f) + x2*__ldg(gat_W+32+f);
                hrow[f] = hv;
                es += hv * __ldg(a_src+f);
                ed += hv * __ldg(a_dst+f);
            }
#pragma unroll
            for (int i = 0; i < 4; i++)
                *(float4*)(A_h + tid*20 + i*4) = make_float4(hrow[4*i], hrow[4*i+1], hrow[4*i+2], hrow[4*i+3]);
            A_e[tid] = es;
            A_e[48 + tid] = ed;
        }
        __syncwarp();
        if (tid < 48) {
            int w = tid >> 4;
            float ed = A_e[48 + tid];
            float vals[16], mx = -1e30f;
#pragma unroll
            for (int s = 0; s < 16; s++) {
                float e = A_e[w * 16 + s] + ed;
                e = (e > 0.f) ? e : 0.2f * e;
                vals[s] = e; mx = fmaxf(mx, e);
            }
            float sum = 0.f;
#pragma unroll
            for (int s = 0; s < 16; s++) { vals[s] = __expf(vals[s] - mx); sum += vals[s]; }
            float inv = 1.f / sum;
            ull acc[8] = {0,0,0,0,0,0,0,0};
#pragma unroll
            for (int ss = 0; ss < 16; ss++) {
                const float4* hr = (const float4*)(A_h + (w * 16 + ss) * 20);
                ull av = pk2(vals[ss] * inv, vals[ss] * inv);
#pragma unroll
                for (int i = 0; i < 4; i++) {
                    float4 hv = hr[i];
                    acc[2*i]   = ffma2(av, pk2(hv.x, hv.y), acc[2*i]);
                    acc[2*i+1] = ffma2(av, pk2(hv.z, hv.w), acc[2*i+1]);
                }
            }
            ull xp[8];
#pragma unroll
            for (int i = 0; i < 8; i++) {
                float2 v = upk2(acc[i]);
                float a = (v.x > 0.f) ? v.x : (__expf(v.x) - 1.f);
                float b = (v.y > 0.f) ? v.y : (__expf(v.y) - 1.f);
                xp[i] = pk2(a, b);
            }
            float y[16];
#pragma unroll
            for (int d = 0; d < 16; d++)
                y[d] = __ldg(te_b + d) + __ldg(pe + w * 16 + d) +
                       dot16g(xp, (const float4*)(te_W + d * 16));
#pragma unroll
            for (int i = 0; i < 4; i++)
                *(float4*)(A_xe + tid*20 + i*4) = make_float4(y[4*i], y[4*i+1], y[4*i+2], y[4*i+3]);
        }
    } else {
        // ======== concurrent weight staging (warps 2-15) ========
        const int tid2 = tid - 64;
        const float4* s1 = (const float4*)qkv_W;  float4* d1 = (float4*)s_qkvW;
        for (int i = tid2; i < 384; i += 448) d1[i] = __ldg(s1 + i);
        const float4* s2 = (const float4*)out_W;  float4* d2 = (float4*)s_outW;
        for (int i = tid2; i < 128; i += 448) d2[i] = __ldg(s2 + i);
        const float4* s3 = (const float4*)ff1_W;  float4* d3 = (float4*)s_ff1W;
        for (int i = tid2; i < 512; i += 448) d3[i] = __ldg(s3 + i);
        const float4* s4 = (const float4*)ff2_W;     // remap to stride 68, float4
        for (int i = tid2; i < 512; i += 448)
            *(float4*)(s_ff2W + (i >> 4) * 68 + (i & 15) * 4) = __ldg(s4 + i);
        if (tid2 < 96)  s_qkvb[tid2] = __ldg(qkv_b + tid2);
        if (tid2 >= 96 && tid2 < 128)  s_outb[tid2-96]  = __ldg(out_b + tid2-96);
        if (tid2 >= 128 && tid2 < 160) s_ln1g[tid2-128] = __ldg(ln1_g + tid2-128);
        if (tid2 >= 160 && tid2 < 192) s_ln1b[tid2-160] = __ldg(ln1_b + tid2-160);
        if (tid2 >= 192 && tid2 < 320) s_ff1b[tid2-192] = __ldg(ff1_b + tid2-192);
        if (tid2 >= 320 && tid2 < 352) s_ff2b[tid2-320] = __ldg(ff2_b + tid2-320);
        if (tid2 >= 352 && tid2 < 384) s_ln2g[tid2-352] = __ldg(ln2_g + tid2-352);
        if (tid2 >= 384 && tid2 < 416) s_ln2b[tid2-384] = __ldg(ln2_b + tid2-384);
    }
    __syncthreads();

    const float inv_sqrt_hd = 0.35355339059327373f;

    for (int l = 0; l < 2; l++) {
        // ---- qkv (6 outputs per active lane; uniform weight rows) ----
        if (tok_ok) {
            ull xp[8]; loadx(A_xe + tk * 20, xp);
#pragma unroll
            for (int i6 = 0; i6 < 6; i6++) {
                int j = pp + i6 * 8;
                A_qkv[tk * 52 + j] = s_qkvb[l * 48 + j] +
                    dot16p(xp, (const float4*)(s_qkvW + l * 768 + j * 16));
            }
        }
        __syncthreads();

        // ---- attention + out-proj + residual + LN1 (192 threads = 4/token) ----
        if (tid < 192) {
            const int tk2 = tid >> 2;
            const int q4  = tid & 3;
            const int h2  = q4 >> 1;
            const int hf  = q4 & 1;
            const int b   = tk2 & 15;
            float4 qv = *(const float4*)(A_qkv + tk2 * 52 + h2 * 8 + hf * 4);
            float sc[3], mx = -1e30f;
#pragma unroll
            for (int ks = 0; ks < 3; ks++) {
                float4 kv = *(const float4*)(A_qkv + (ks * 16 + b) * 52 + 16 + h2 * 8 + hf * 4);
                float p = qv.x*kv.x + qv.y*kv.y + qv.z*kv.z + qv.w*kv.w;
                p += __shfl_xor_sync(0xffffffffu, p, 1);
                p *= inv_sqrt_hd;
                sc[ks] = p; mx = fmaxf(mx, p);
            }
            float sum = 0.f;
#pragma unroll
            for (int ks = 0; ks < 3; ks++) { sc[ks] = __expf(sc[ks] - mx); sum += sc[ks]; }
            float inv = 1.f / sum;
            float c0 = 0.f, c1 = 0.f, c2 = 0.f, c3 = 0.f;
#pragma unroll
            for (int ks = 0; ks < 3; ks++) {
                float4 vv = *(const float4*)(A_qkv + (ks * 16 + b) * 52 + 32 + h2 * 8 + hf * 4);
                float w = sc[ks];
                c0 += w * vv.x; c1 += w * vv.y; c2 += w * vv.z; c3 += w * vv.w;
            }
            c0 *= inv; c1 *= inv; c2 *= inv; c3 *= inv;
            float part[16];
#pragma unroll
            for (int d = 0; d < 16; d++) {
                float4 w = *(const float4*)(s_outW + l * 256 + d * 16 + q4 * 4);
                part[d] = c0*w.x + c1*w.y + c2*w.z + c3*w.w;
            }
            const int bm = (q4 < 2) ? 0 : 8;
            const int bo = 8 - bm;
            float s1v[8];
#pragma unroll
            for (int i = 0; i < 8; i++)
                s1v[i] = part[bm + i] + __shfl_xor_sync(0xffffffffu, part[bo + i], 2);
            const int mr = (q4 & 1) * 4;
            const int orr = 4 - mr;
            float y[4];
#pragma unroll
            for (int k = 0; k < 4; k++)
                y[k] = s1v[mr + k] + __shfl_xor_sync(0xffffffffu, s1v[orr + k], 1);
            float4 resid = *(const float4*)(A_xe + tk2 * 20 + q4 * 4);
            y[0] += resid.x + s_outb[l*16 + q4*4 + 0];
            y[1] += resid.y + s_outb[l*16 + q4*4 + 1];
            y[2] += resid.z + s_outb[l*16 + q4*4 + 2];
            y[3] += resid.w + s_outb[l*16 + q4*4 + 3];
            float ls = y[0]+y[1]+y[2]+y[3];
            float lq = y[0]*y[0]+y[1]*y[1]+y[2]*y[2]+y[3]*y[3];
            ls += __shfl_xor_sync(0xffffffffu, ls, 1);
            lq += __shfl_xor_sync(0xffffffffu, lq, 1);
            ls += __shfl_xor_sync(0xffffffffu, ls, 2);
            lq += __shfl_xor_sync(0xffffffffu, lq, 2);
            float m = ls * 0.0625f;
            float rin = rsqrtf(lq * 0.0625f - m * m + 1e-5f);
#pragma unroll
            for (int k = 0; k < 4; k++) {
                int d = q4 * 4 + k;
                y[k] = (y[k] - m) * rin * s_ln1g[l * 16 + d] + s_ln1b[l * 16 + d];
            }
            *(float4*)(A_xe + tk2 * 20 + q4 * 4) = make_float4(y[0], y[1], y[2], y[3]);
        }
        __syncthreads();

        // ---- ff1 (relu), 8 contiguous outputs per active lane ----
        if (tok_ok) {
            ull xp[8]; loadx(A_xe + tk * 20, xp);
            float y[8];
#pragma unroll
            for (int k = 0; k < 8; k++) {
                int f = pp * 8 + k;
                y[k] = fmaxf(s_ff1b[l * 64 + f] +
                             dot16p(xp, (const float4*)(s_ff1W + l * 1024 + f * 16)), 0.f);
            }
            *(float4*)(A_hid + tk * 68 + pp * 8)     = make_float4(y[0], y[1], y[2], y[3]);
            *(float4*)(A_hid + tk * 68 + pp * 8 + 4) = make_float4(y[4], y[5], y[6], y[7]);
        }
        __syncthreads();

        // ---- ff2 + residual + LN2 (384 threads = 8/token; K split across kh) ----
        if (tid < 384) {
            const int tk2 = tid >> 3;          // token
            const int q8  = tid & 7;
            const int og  = q8 & 3;            // output group: d = og + 4k
            const int kh  = q8 >> 2;           // K-half
            const float4* hr  = (const float4*)(A_hid + tk2 * 68 + kh * 32);
            const float4* wr0 = (const float4*)(s_ff2W + l * 1088 + (og + 0)  * 68 + kh * 32);
            const float4* wr1 = (const float4*)(s_ff2W + l * 1088 + (og + 4)  * 68 + kh * 32);
            const float4* wr2 = (const float4*)(s_ff2W + l * 1088 + (og + 8)  * 68 + kh * 32);
            const float4* wr3 = (const float4*)(s_ff2W + l * 1088 + (og + 12) * 68 + kh * 32);
            ull a0[4] = {0,0,0,0}, a1[4] = {0,0,0,0};
            const int rot = kh * 4;            // bank-stagger between K-halves
#pragma unroll
            for (int i = 0; i < 8; i++) {
                int c = (i + rot) & 7;
                float4 h4 = hr[c];
                ull h0 = pk2(h4.x, h4.y), h1 = pk2(h4.z, h4.w);
                float4 w0 = wr0[c], w1 = wr1[c], w2 = wr2[c], w3 = wr3[c];
                a0[0] = ffma2(h0, pk2(w0.x, w0.y), a0[0]); a1[0] = ffma2(h1, pk2(w0.z, w0.w), a1[0]);
                a0[1] = ffma2(h0, pk2(w1.x, w1.y), a0[1]); a1[1] = ffma2(h1, pk2(w1.z, w1.w), a1[1]);
                a0[2] = ffma2(h0, pk2(w2.x, w2.y), a0[2]); a1[2] = ffma2(h1, pk2(w2.z, w2.w), a1[2]);
                a0[3] = ffma2(h0, pk2(w3.x, w3.y), a0[3]); a1[3] = ffma2(h1, pk2(w3.z, w3.w), a1[3]);
            }
            // combine K-halves with partner (lane xor 4; tokens are 8-lane aligned)
            float y[4], ls = 0.f, lq = 0.f;
#pragma unroll
            for (int k = 0; k < 4; k++) {
                float2 s0 = upk2(a0[k]), s1 = upk2(a1[k]);
                float part = (s0.x + s1.x) + (s0.y + s1.y);
                part += __shfl_xor_sync(0xffffffffu, part, 4);
                int d = og + 4 * k;
                y[k] = part + s_ff2b[l * 16 + d] + A_xe[tk2 * 20 + d];
                ls += y[k]; lq += y[k] * y[k];
            }
            // LN reduce across og (both kh groups hold identical y -> reduce within kh)
            ls += __shfl_xor_sync(0xffffffffu, ls, 1);
            lq += __shfl_xor_sync(0xffffffffu, lq, 1);
            ls += __shfl_xor_sync(0xffffffffu, ls, 2);
            lq += __shfl_xor_sync(0xffffffffu, lq, 2);
            float m = ls * 0.0625f;
            float rin = rsqrtf(lq * 0.0625f - m * m + 1e-5f);
            if (kh == 0) {
#pragma unroll
                for (int k = 0; k < 4; k++) {
                    int d = og + 4 * k;
                    A_xe[tk2 * 20 + d] = (y[k] - m) * rin * s_ln2g[l * 16 + d] + s_ln2b[l * 16 + d];
                }
            }
        }
        __syncthreads();
    }

    // ---- decoder: warp = output row, latent from smem ----
    {
        ull a0 = 0ull, a1 = 0ull;
#pragma unroll
        for (int i = 0; i < 6; i++) {
            int j = i * 128 + 4 * lane;
            int n = j / 48, rem = j - n * 48;
            int ww = rem >> 4, d = rem & 15;
            float4 x = *(const float4*)(A_xe + (ww * 16 + n) * 20 + d);
            a0 = ffma2(pk2(x.x, x.y), pk2(wreg[i].x, wreg[i].y), a0);
            a1 = ffma2(pk2(x.z, x.w), pk2(wreg[i].z, wreg[i].w), a1);
        }
        float2 s0 = upk2(a0), s1 = upk2(a1);
        float s = (s0.x + s1.x) + (s0.y + s1.y);
#pragma unroll
        for (int o = 16; o; o >>= 1) s += __shfl_xor_sync(0xffffffffu, s, o);
        if (lane == 0) {
            s += bias_reg;
            if (row >= 32) s = 1.f / (1.f + __expf(-s));
            out[row] = s;
        }
    }
}

extern "C" void kernel_launch(void* const* d_in, const int* in_sizes, int n_in,
                              void* d_out, int out_size) {
    const int smem_bytes = 14464 * 4;
    cudaFuncSetAttribute(fused_kernel, cudaFuncAttributeMaxDynamicSharedMemorySize, smem_bytes);
    fused_kernel<<<10, NT, smem_bytes>>>(
        (const float*)d_in[0],
        (const float*)d_in[2], (const float*)d_in[3], (const float*)d_in[4],
        (const float*)d_in[5], (const float*)d_in[6], (const float*)d_in[7],
        (const float*)d_in[8], (const float*)d_in[9],
        (const float*)d_in[10], (const float*)d_in[11],
        (const float*)d_in[12], (const float*)d_in[13],
        (const float*)d_in[14], (const float*)d_in[15],
        (const float*)d_in[16], (const float*)d_in[17],
        (const float*)d_in[18], (const float*)d_in[19],
        (const float*)d_in[20], (const float*)d_in[21],
        (const float*)d_in[22], (const float*)d_in[23],
        (float*)d_out);
}

// round 17
// speedup vs baseline: 1.2959x; 1.0022x over previous
#include <cuda_runtime.h>
#include <math.h>

#define NT 512
typedef unsigned long long ull;

// ---- packed f32x2 helpers (sm_103a) ----
__device__ __forceinline__ ull pk2(float lo, float hi) {
    ull r; asm("mov.b64 %0, {%1,%2};" : "=l"(r) : "f"(lo), "f"(hi)); return r;
}
__device__ __forceinline__ float2 upk2(ull v) {
    float2 r; asm("mov.b64 {%0,%1}, %2;" : "=f"(r.x), "=f"(r.y) : "l"(v)); return r;
}
__device__ __forceinline__ ull ffma2(ull a, ull b, ull c) {
    ull d; asm("fma.rn.f32x2 %0, %1, %2, %3;" : "=l"(d) : "l"(a), "l"(b), "l"(c)); return d;
}
__device__ __forceinline__ void loadx(const float* p, ull* xp) {
    const float4* p4 = (const float4*)p;
#pragma unroll
    for (int i = 0; i < 4; i++) {
        float4 v = p4[i];
        xp[2*i]   = pk2(v.x, v.y);
        xp[2*i+1] = pk2(v.z, v.w);
    }
}
__device__ __forceinline__ float dot16p(const ull* xp, const float4* w4) {
    ull a0 = 0ull, a1 = 0ull;
#pragma unroll
    for (int i = 0; i < 4; i++) {
        float4 w = w4[i];
        a0 = ffma2(xp[2*i],   pk2(w.x, w.y), a0);
        a1 = ffma2(xp[2*i+1], pk2(w.z, w.w), a1);
    }
    float2 s0 = upk2(a0), s1 = upk2(a1);
    return (s0.x + s1.x) + (s0.y + s1.y);
}
__device__ __forceinline__ float dot16g(const ull* xp, const float4* __restrict__ w4) {
    float4 w0 = __ldg(w4), w1 = __ldg(w4+1), w2 = __ldg(w4+2), w3 = __ldg(w4+3);
    ull a0 = 0ull, a1 = 0ull;
    a0 = ffma2(xp[0], pk2(w0.x, w0.y), a0); a1 = ffma2(xp[1], pk2(w0.z, w0.w), a1);
    a0 = ffma2(xp[2], pk2(w1.x, w1.y), a0); a1 = ffma2(xp[3], pk2(w1.z, w1.w), a1);
    a0 = ffma2(xp[4], pk2(w2.x, w2.y), a0); a1 = ffma2(xp[5], pk2(w2.z, w2.w), a1);
    a0 = ffma2(xp[6], pk2(w3.x, w3.y), a0); a1 = ffma2(xp[7], pk2(w3.z, w3.w), a1);
    float2 s0 = upk2(a0), s1 = upk2(a1);
    return (s0.x + s1.x) + (s0.y + s1.y);
}

__global__ __launch_bounds__(NT, 1) void fused_kernel(
    const float* __restrict__ t,
    const float* __restrict__ gat_W, const float* __restrict__ a_src, const float* __restrict__ a_dst,
    const float* __restrict__ te_W, const float* __restrict__ te_b, const float* __restrict__ pe,
    const float* __restrict__ qkv_W, const float* __restrict__ qkv_b,
    const float* __restrict__ out_W, const float* __restrict__ out_b,
    const float* __restrict__ ln1_g, const float* __restrict__ ln1_b,
    const float* __restrict__ ff1_W, const float* __restrict__ ff1_b,
    const float* __restrict__ ff2_W, const float* __restrict__ ff2_b,
    const float* __restrict__ ln2_g, const float* __restrict__ ln2_b,
    const float* __restrict__ an_W, const float* __restrict__ an_b,
    const float* __restrict__ pr_W, const float* __restrict__ pr_b,
    float* __restrict__ out)
{
    const int tid  = threadIdx.x;
    const int warp = tid >> 5;
    const int lane = tid & 31;
    const int g    = warp & 1;
    const int tk   = g * 32 + lane;
    const int pp   = warp >> 1;
    const bool tok_ok = tk < 48;

    // ---- decoder weight prefetch (registers; hidden behind encoder) ----
    const int row = blockIdx.x * 16 + warp;   // 0..159
    const float4* wp = (row < 32) ? (const float4*)(an_W + row * 768)
                                  : (const float4*)(pr_W + (row - 32) * 768);
    float bias_reg = (row < 32) ? an_b[row] : pr_b[row - 32];
    float4 wreg[6];
#pragma unroll
    for (int i = 0; i < 6; i++) wreg[i] = __ldg(wp + i * 32 + lane);

    extern __shared__ float sm[];
    float* s_qkvW = sm;            // 1536
    float* s_qkvb = sm + 1536;     // 96
    float* s_outW = sm + 1632;     // 512
    float* s_outb = sm + 2144;     // 32
    float* s_ln1g = sm + 2176;     // 32
    float* s_ln1b = sm + 2208;     // 32
    float* s_ff1W = sm + 2240;     // 2048
    float* s_ff1b = sm + 4288;     // 128
    float* s_ff2W = sm + 4416;     // 2176 (stride 68)
    float* s_ff2b = sm + 6592;     // 32
    float* s_ln2g = sm + 6624;     // 32
    float* s_ln2b = sm + 6656;     // 32
    float* A_h    = sm + 6688;     // 48*20
    float* A_xe   = sm + 7648;     // 48*20
    float* A_qkv  = sm + 8608;     // 48*52
    float* A_hid  = sm + 11104;    // 48*68
    float* A_e    = sm + 14368;    // 96

    if (warp < 2) {
        // ======== overlapped prologue: GAT P1 + P2 (weights from L2) ========
        if (tid < 48) {
            float x0 = __ldg(t + tid*3), x1 = __ldg(t + tid*3 + 1), x2 = __ldg(t + tid*3 + 2);
            float hrow[16];
            float es = 0.f, ed = 0.f;
#pragma unroll
            for (int f = 0; f < 16; f++) {
                float hv = x0*__ldg(gat_W+f) + x1*__ldg(gat_W+16+f) + x2*__ldg(gat_W+32+f);
                hrow[f] = hv;
                es += hv * __ldg(a_src+f);
                ed += hv * __ldg(a_dst+f);
            }
#pragma unroll
            for (int i = 0; i < 4; i++)
                *(float4*)(A_h + tid*20 + i*4) = make_float4(hrow[4*i], hrow[4*i+1], hrow[4*i+2], hrow[4*i+3]);
            A_e[tid] = es;
            A_e[48 + tid] = ed;
        }
        __syncwarp();
        if (tid < 48) {
            int w = tid >> 4;
            float ed = A_e[48 + tid];
            float vals[16], mx = -1e30f;
#pragma unroll
            for (int s = 0; s < 16; s++) {
                float e = A_e[w * 16 + s] + ed;
                e = (e > 0.f) ? e : 0.2f * e;
                vals[s] = e; mx = fmaxf(mx, e);
            }
            float sum = 0.f;
#pragma unroll
            for (int s = 0; s < 16; s++) { vals[s] = __expf(vals[s] - mx); sum += vals[s]; }
            float inv = 1.f / sum;
            ull acc[8] = {0,0,0,0,0,0,0,0};
#pragma unroll
            for (int ss = 0; ss < 16; ss++) {
                const float4* hr = (const float4*)(A_h + (w * 16 + ss) * 20);
                ull av = pk2(vals[ss] * inv, vals[ss] * inv);
#pragma unroll
                for (int i = 0; i < 4; i++) {
                    float4 hv = hr[i];
                    acc[2*i]   = ffma2(av, pk2(hv.x, hv.y), acc[2*i]);
                    acc[2*i+1] = ffma2(av, pk2(hv.z, hv.w), acc[2*i+1]);
                }
            }
            ull xp[8];
#pragma unroll
            for (int i = 0; i < 8; i++) {
                float2 v = upk2(acc[i]);
                float a = (v.x > 0.f) ? v.x : (__expf(v.x) - 1.f);
                float b = (v.y > 0.f) ? v.y : (__expf(v.y) - 1.f);
                xp[i] = pk2(a, b);
            }
            float y[16];
#pragma unroll
            for (int d = 0; d < 16; d++)
                y[d] = __ldg(te_b + d) + __ldg(pe + w * 16 + d) +
                       dot16g(xp, (const float4*)(te_W + d * 16));
#pragma unroll
            for (int i = 0; i < 4; i++)
                *(float4*)(A_xe + tid*20 + i*4) = make_float4(y[4*i], y[4*i+1], y[4*i+2], y[4*i+3]);
        }
    } else {
        // ======== concurrent weight staging (warps 2-15) ========
        const int tid2 = tid - 64;
        const float4* s1 = (const float4*)qkv_W;  float4* d1 = (float4*)s_qkvW;
        for (int i = tid2; i < 384; i += 448) d1[i] = __ldg(s1 + i);
        const float4* s2 = (const float4*)out_W;  float4* d2 = (float4*)s_outW;
        for (int i = tid2; i < 128; i += 448) d2[i] = __ldg(s2 + i);
        const float4* s3 = (const float4*)ff1_W;  float4* d3 = (float4*)s_ff1W;
        for (int i = tid2; i < 512; i += 448) d3[i] = __ldg(s3 + i);
        const float4* s4 = (const float4*)ff2_W;     // remap to stride 68, float4
        for (int i = tid2; i < 512; i += 448)
            *(float4*)(s_ff2W + (i >> 4) * 68 + (i & 15) * 4) = __ldg(s4 + i);
        if (tid2 < 96)  s_qkvb[tid2] = __ldg(qkv_b + tid2);
        if (tid2 >= 96 && tid2 < 128)  s_outb[tid2-96]  = __ldg(out_b + tid2-96);
        if (tid2 >= 128 && tid2 < 160) s_ln1g[tid2-128] = __ldg(ln1_g + tid2-128);
        if (tid2 >= 160 && tid2 < 192) s_ln1b[tid2-160] = __ldg(ln1_b + tid2-160);
        if (tid2 >= 192 && tid2 < 320) s_ff1b[tid2-192] = __ldg(ff1_b + tid2-192);
        if (tid2 >= 320 && tid2 < 352) s_ff2b[tid2-320] = __ldg(ff2_b + tid2-320);
        if (tid2 >= 352 && tid2 < 384) s_ln2g[tid2-352] = __ldg(ln2_g + tid2-352);
        if (tid2 >= 384 && tid2 < 416) s_ln2b[tid2-384] = __ldg(ln2_b + tid2-384);
    }
    __syncthreads();

    const float inv_sqrt_hd = 0.35355339059327373f;

    for (int l = 0; l < 2; l++) {
        // ---- qkv (6 outputs per active lane; uniform weight rows) ----
        if (tok_ok) {
            ull xp[8]; loadx(A_xe + tk * 20, xp);
#pragma unroll
            for (int i6 = 0; i6 < 6; i6++) {
                int j = pp + i6 * 8;
                A_qkv[tk * 52 + j] = s_qkvb[l * 48 + j] +
                    dot16p(xp, (const float4*)(s_qkvW + l * 768 + j * 16));
            }
        }
        __syncthreads();

        // ---- attention + out-proj + residual + LN1 (192 threads = 4/token) ----
        if (tid < 192) {
            const int tk2 = tid >> 2;
            const int q4  = tid & 3;
            const int h2  = q4 >> 1;
            const int hf  = q4 & 1;
            const int b   = tk2 & 15;
            float4 qv = *(const float4*)(A_qkv + tk2 * 52 + h2 * 8 + hf * 4);
            float sc[3], mx = -1e30f;
#pragma unroll
            for (int ks = 0; ks < 3; ks++) {
                float4 kv = *(const float4*)(A_qkv + (ks * 16 + b) * 52 + 16 + h2 * 8 + hf * 4);
                float p = qv.x*kv.x + qv.y*kv.y + qv.z*kv.z + qv.w*kv.w;
                p += __shfl_xor_sync(0xffffffffu, p, 1);
                p *= inv_sqrt_hd;
                sc[ks] = p; mx = fmaxf(mx, p);
            }
            float sum = 0.f;
#pragma unroll
            for (int ks = 0; ks < 3; ks++) { sc[ks] = __expf(sc[ks] - mx); sum += sc[ks]; }
            float inv = 1.f / sum;
            float c0 = 0.f, c1 = 0.f, c2 = 0.f, c3 = 0.f;
#pragma unroll
            for (int ks = 0; ks < 3; ks++) {
                float4 vv = *(const float4*)(A_qkv + (ks * 16 + b) * 52 + 32 + h2 * 8 + hf * 4);
                float w = sc[ks];
                c0 += w * vv.x; c1 += w * vv.y; c2 += w * vv.z; c3 += w * vv.w;
            }
            c0 *= inv; c1 *= inv; c2 *= inv; c3 *= inv;
            float part[16];
#pragma unroll
            for (int d = 0; d < 16; d++) {
                float4 w = *(const float4*)(s_outW + l * 256 + d * 16 + q4 * 4);
                part[d] = c0*w.x + c1*w.y + c2*w.z + c3*w.w;
            }
            const int bm = (q4 < 2) ? 0 : 8;
            const int bo = 8 - bm;
            float s1v[8];
#pragma unroll
            for (int i = 0; i < 8; i++)
                s1v[i] = part[bm + i] + __shfl_xor_sync(0xffffffffu, part[bo + i], 2);
            const int mr = (q4 & 1) * 4;
            const int orr = 4 - mr;
            float y[4];
#pragma unroll
            for (int k = 0; k < 4; k++)
                y[k] = s1v[mr + k] + __shfl_xor_sync(0xffffffffu, s1v[orr + k], 1);
            float4 resid = *(const float4*)(A_xe + tk2 * 20 + q4 * 4);
            y[0] += resid.x + s_outb[l*16 + q4*4 + 0];
            y[1] += resid.y + s_outb[l*16 + q4*4 + 1];
            y[2] += resid.z + s_outb[l*16 + q4*4 + 2];
            y[3] += resid.w + s_outb[l*16 + q4*4 + 3];
            float ls = y[0]+y[1]+y[2]+y[3];
            float lq = y[0]*y[0]+y[1]*y[1]+y[2]*y[2]+y[3]*y[3];
            ls += __shfl_xor_sync(0xffffffffu, ls, 1);
            lq += __shfl_xor_sync(0xffffffffu, lq, 1);
            ls += __shfl_xor_sync(0xffffffffu, ls, 2);
            lq += __shfl_xor_sync(0xffffffffu, lq, 2);
            float m = ls * 0.0625f;
            float rin = rsqrtf(lq * 0.0625f - m * m + 1e-5f);
#pragma unroll
            for (int k = 0; k < 4; k++) {
                int d = q4 * 4 + k;
                y[k] = (y[k] - m) * rin * s_ln1g[l * 16 + d] + s_ln1b[l * 16 + d];
            }
            *(float4*)(A_xe + tk2 * 20 + q4 * 4) = make_float4(y[0], y[1], y[2], y[3]);
        }
        __syncthreads();

        // ---- ff1 (relu), 8 contiguous outputs per active lane ----
        if (tok_ok) {
            ull xp[8]; loadx(A_xe + tk * 20, xp);
            float y[8];
#pragma unroll
            for (int k = 0; k < 8; k++) {
                int f = pp * 8 + k;
                y[k] = fmaxf(s_ff1b[l * 64 + f] +
                             dot16p(xp, (const float4*)(s_ff1W + l * 1024 + f * 16)), 0.f);
            }
            *(float4*)(A_hid + tk * 68 + pp * 8)     = make_float4(y[0], y[1], y[2], y[3]);
            *(float4*)(A_hid + tk * 68 + pp * 8 + 4) = make_float4(y[4], y[5], y[6], y[7]);
        }
        __syncthreads();

        // ---- ff2 + residual + LN2 (384 threads = 8/token; K split across kh) ----
        if (tid < 384) {
            const int tk2 = tid >> 3;          // token
            const int q8  = tid & 7;
            const int og  = q8 & 3;            // output group: d = og + 4k
            const int kh  = q8 >> 2;           // K-half
            const float4* hr  = (const float4*)(A_hid + tk2 * 68 + kh * 32);
            const float4* wr0 = (const float4*)(s_ff2W + l * 1088 + (og + 0)  * 68 + kh * 32);
            const float4* wr1 = (const float4*)(s_ff2W + l * 1088 + (og + 4)  * 68 + kh * 32);
            const float4* wr2 = (const float4*)(s_ff2W + l * 1088 + (og + 8)  * 68 + kh * 32);
            const float4* wr3 = (const float4*)(s_ff2W + l * 1088 + (og + 12) * 68 + kh * 32);
            ull a0[4] = {0,0,0,0}, a1[4] = {0,0,0,0};
            const int rot = kh * 4;            // bank-stagger between K-halves
#pragma unroll
            for (int i = 0; i < 8; i++) {
                int c = (i + rot) & 7;
                float4 h4 = hr[c];
                ull h0 = pk2(h4.x, h4.y), h1 = pk2(h4.z, h4.w);
                float4 w0 = wr0[c], w1 = wr1[c], w2 = wr2[c], w3 = wr3[c];
                a0[0] = ffma2(h0, pk2(w0.x, w0.y), a0[0]); a1[0] = ffma2(h1, pk2(w0.z, w0.w), a1[0]);
                a0[1] = ffma2(h0, pk2(w1.x, w1.y), a0[1]); a1[1] = ffma2(h1, pk2(w1.z, w1.w), a1[1]);
                a0[2] = ffma2(h0, pk2(w2.x, w2.y), a0[2]); a1[2] = ffma2(h1, pk2(w2.z, w2.w), a1[2]);
                a0[3] = ffma2(h0, pk2(w3.x, w3.y), a0[3]); a1[3] = ffma2(h1, pk2(w3.z, w3.w), a1[3]);
            }
            // combine K-halves with partner (lane xor 4; tokens are 8-lane aligned)
            float y[4], ls = 0.f, lq = 0.f;
#pragma unroll
            for (int k = 0; k < 4; k++) {
                float2 s0 = upk2(a0[k]), s1 = upk2(a1[k]);
                float part = (s0.x + s1.x) + (s0.y + s1.y);
                part += __shfl_xor_sync(0xffffffffu, part, 4);
                int d = og + 4 * k;
                y[k] = part + s_ff2b[l * 16 + d] + A_xe[tk2 * 20 + d];
                ls += y[k]; lq += y[k] * y[k];
            }
            // LN reduce across og (both kh groups hold identical y -> reduce within kh)
            ls += __shfl_xor_sync(0xffffffffu, ls, 1);
            lq += __shfl_xor_sync(0xffffffffu, lq, 1);
            ls += __shfl_xor_sync(0xffffffffu, ls, 2);
            lq += __shfl_xor_sync(0xffffffffu, lq, 2);
            float m = ls * 0.0625f;
            float rin = rsqrtf(lq * 0.0625f - m * m + 1e-5f);
            if (kh == 0) {
#pragma unroll
                for (int k = 0; k < 4; k++) {
                    int d = og + 4 * k;
                    A_xe[tk2 * 20 + d] = (y[k] - m) * rin * s_ln2g[l * 16 + d] + s_ln2b[l * 16 + d];
                }
            }
        }
        __syncthreads();
    }

    // ---- decoder: warp = output row, latent from smem ----
    {
        ull a0 = 0ull, a1 = 0ull;
#pragma unroll
        for (int i = 0; i < 6; i++) {
            int j = i * 128 + 4 * lane;
            int n = j / 48, rem = j - n * 48;
            int ww = rem >> 4, d = rem & 15;
            float4 x = *(const float4*)(A_xe + (ww * 16 + n) * 20 + d);
            a0 = ffma2(pk2(x.x, x.y), pk2(wreg[i].x, wreg[i].y), a0);
            a1 = ffma2(pk2(x.z, x.w), pk2(wreg[i].z, wreg[i].w), a1);
        }
        float2 s0 = upk2(a0), s1 = upk2(a1);
        float s = (s0.x + s1.x) + (s0.y + s1.y);
#pragma unroll
        for (int o = 16; o; o >>= 1) s += __shfl_xor_sync(0xffffffffu, s, o);
        if (lane == 0) {
            s += bias_reg;
            if (row >= 32) s = 1.f / (1.f + __expf(-s));
            out[row] = s;
        }
    }
}

extern "C" void kernel_launch(void* const* d_in, const int* in_sizes, int n_in,
                              void* d_out, int out_size) {
    const int smem_bytes = 14464 * 4;
    cudaFuncSetAttribute(fused_kernel, cudaFuncAttributeMaxDynamicSharedMemorySize, smem_bytes);
    fused_kernel<<<10, NT, smem_bytes>>>(
        (const float*)d_in[0],
        (const float*)d_in[2], (const float*)d_in[3], (const float*)d_in[4],
        (const float*)d_in[5], (const float*)d_in[6], (const float*)d_in[7],
        (const float*)d_in[8], (const float*)d_in[9],
        (const float*)d_in[10], (const float*)d_in[11],
        (const float*)d_in[12], (const float*)d_in[13],
        (const float*)d_in[14], (const float*)d_in[15],
        (const float*)d_in[16], (const float*)d_in[17],
        (const float*)d_in[18], (const float*)d_in[19],
        (const float*)d_in[20], (const float*)d_in[21],
        (const float*)d_in[22], (const float*)d_in[23],
        (float*)d_out);
}